// round 16
// baseline (speedup 1.0000x reference)
#include <cuda_runtime.h>
#include <cuda_fp16.h>
#include <math.h>
#include <stdint.h>

#define DIM    512
#define NNEUR  4096
#define BT     8192   // B*T
#define NBLK1  (NNEUR / 128)   // 32 column-blocks in GEMM1

// ---------------- scratch (device globals; allocation-free) ----------------
__device__ float                g_p2[NNEUR];
__device__ float                g_x2[BT];
__device__ float                g_cvec[DIM];
__device__ __align__(16) float  g_psum[(size_t)BT * NBLK1];     // 1 MB
__device__ __align__(16) __half g_xh[BT * DIM];                 // 8 MB
__device__ __align__(16) __half g_ph[NNEUR * DIM];              // 4 MB
__device__ __align__(16) __half g_wvh[DIM * DIM];               // 0.5 MB
__device__ __align__(16) __half g_woh[DIM * DIM];               // 0.5 MB
__device__ __align__(16) __half g_valh[NNEUR * DIM];            // 4 MB  values
__device__ __align__(16) __half g_w2h[DIM * NNEUR];             // 4 MB  W2^T
__device__ __align__(16) __half g_attn[(size_t)BT * NNEUR];     // 64 MB (e = exp)

// ---------------- warp-mma helpers (base ISA: sm_80+, no 'a' suffix) -------
__device__ __forceinline__ uint32_t smem_to_u32(const void* p) {
    uint32_t a;
    asm("{ .reg .u64 t; cvta.to.shared.u64 t, %1; cvt.u32.u64 %0, t; }" : "=r"(a) : "l"(p));
    return a;
}
__device__ __forceinline__ void ldsm4(uint32_t& r0, uint32_t& r1, uint32_t& r2,
                                      uint32_t& r3, uint32_t addr) {
    asm volatile("ldmatrix.sync.aligned.m8n8.x4.shared.b16 {%0,%1,%2,%3}, [%4];"
                 : "=r"(r0), "=r"(r1), "=r"(r2), "=r"(r3) : "r"(addr));
}
// f16 inputs, f32 accumulators
__device__ __forceinline__ void mma16816f(float* c, const uint32_t* a,
                                          uint32_t b0, uint32_t b1) {
    asm volatile(
        "mma.sync.aligned.m16n8k16.row.col.f32.f16.f16.f32 "
        "{%0,%1,%2,%3}, {%4,%5,%6,%7}, {%8,%9}, {%0,%1,%2,%3};"
        : "+f"(c[0]), "+f"(c[1]), "+f"(c[2]), "+f"(c[3])
        : "r"(a[0]), "r"(a[1]), "r"(a[2]), "r"(a[3]), "r"(b0), "r"(b1));
}
// f16 inputs, f16 accumulators (2 regs of f16x2)
__device__ __forceinline__ void mma16816h(uint32_t* c, const uint32_t* a,
                                          uint32_t b0, uint32_t b1) {
    asm volatile(
        "mma.sync.aligned.m16n8k16.row.col.f16.f16.f16.f16 "
        "{%0,%1}, {%2,%3,%4,%5}, {%6,%7}, {%0,%1};"
        : "+r"(c[0]), "+r"(c[1])
        : "r"(a[0]), "r"(a[1]), "r"(a[2]), "r"(a[3]), "r"(b0), "r"(b1));
}
__device__ __forceinline__ void cp16(uint32_t dst, const void* src) {
    asm volatile("cp.async.cg.shared.global [%0], [%1], 16;" :: "r"(dst), "l"(src));
}
#define CP_COMMIT() asm volatile("cp.async.commit_group;" ::: "memory")
#define CP_WAIT(n)  asm volatile("cp.async.wait_group %0;" :: "n"(n) : "memory")

// swizzled smem offset for 64B rows (4 x 16B chunks), conflict-free ldmatrix
__device__ __forceinline__ uint32_t swz_off(int row, int chunk) {
    return (uint32_t)(row * 64 + ((chunk ^ ((row >> 1) & 3)) << 4));
}

static constexpr int MG_STAGES = 4;
static constexpr int MG_SMEM   = MG_STAGES * 16384;   // 64 KB dynamic

// ---------------------------------------------------------------------------
// Tiling everywhere: BM=128, BN=128, BK=32, 8 warps (2m x 4n), warp 64x32.
// 4-stage cp.async pipeline with const-folded slots.
// ---------------------------------------------------------------------------

// GEMM1: e = exp(interaction(x @ pos^T)), fp16 in, fp16 acc, e -> fp16,
// per-block row sums -> psum.  niter = DIM/32 = 16.
__global__ __launch_bounds__(256) void gemm1_f16(
    const __half* __restrict__ A, const __half* __restrict__ B,
    __half* __restrict__ Ch,
    const float* __restrict__ x2, const float* __restrict__ p2,
    const float* __restrict__ scale, float* __restrict__ psum)
{
    extern __shared__ __align__(128) char dsm[];
    __shared__ float p2s[128], scs[128];
    __shared__ float bsum[4][128];

    const int tid  = threadIdx.x;
    const int lane = tid & 31, wid = tid >> 5;
    const int warp_m = wid >> 2, warp_n = wid & 3;
    const int bm = blockIdx.y * 128, bn = blockIdx.x * 128;
    constexpr int NITER = DIM / 32;    // 16

    if (tid < 128) {
        p2s[tid] = p2[bn + tid];
        scs[tid] = scale[bn + tid];
    }

    const int lrow = tid >> 2;
    const int lchk = tid & 3;
    const uint32_t su = smem_to_u32(dsm);

    auto issue = [&](int slot, int it) {
        const int k0 = it * 32;
        const uint32_t ab = su + slot * 16384;
        const uint32_t bb = ab + 8192;
#pragma unroll
        for (int h = 0; h < 2; h++) {
            const int r = lrow + h * 64;
            cp16(ab + swz_off(r, lchk), A + (size_t)(bm + r) * DIM + k0 + lchk * 8);
            cp16(bb + swz_off(r, lchk), B + (size_t)(bn + r) * DIM + k0 + lchk * 8);
        }
        CP_COMMIT();
    };

    issue(0, 0);
    issue(1, 1);
    issue(2, 2);

    uint32_t acc[4][4][2] = {};
    const int rin = lane & 7, matid = lane >> 3;

    for (int itb = 0; itb < NITER; itb += 4) {
#pragma unroll
        for (int j = 0; j < 4; j++) {
            const int it = itb + j;
            CP_WAIT(2);
            __syncthreads();
            if (it + 3 < NITER) issue((j + 3) & 3, it + 3);

            const uint32_t a_s = su + j * 16384;
            const uint32_t b_s = a_s + 8192;
#pragma unroll
            for (int s = 0; s < 2; s++) {
                uint32_t af[4][4], bf[2][4];
#pragma unroll
                for (int mb = 0; mb < 4; mb++) {
                    const int row = warp_m * 64 + mb * 16 + (matid & 1) * 8 + rin;
                    const int chk = s * 2 + (matid >> 1);
                    ldsm4(af[mb][0], af[mb][1], af[mb][2], af[mb][3], a_s + swz_off(row, chk));
                }
#pragma unroll
                for (int nb2 = 0; nb2 < 2; nb2++) {
                    const int row = warp_n * 32 + nb2 * 16 + (matid >> 1) * 8 + rin;
                    const int chk = s * 2 + (matid & 1);
                    ldsm4(bf[nb2][0], bf[nb2][1], bf[nb2][2], bf[nb2][3], b_s + swz_off(row, chk));
                }
#pragma unroll
                for (int mb = 0; mb < 4; mb++)
#pragma unroll
                    for (int nb = 0; nb < 4; nb++)
                        mma16816h(acc[mb][nb], af[mb],
                                  bf[nb >> 1][(nb & 1) * 2], bf[nb >> 1][(nb & 1) * 2 + 1]);
            }
        }
    }

    // ---- interaction epilogue (fp32 math from unpacked fp16 accs) ----
    const int g = lane >> 2, tig = lane & 3;
    float rs[4][2];
#pragma unroll
    for (int mb = 0; mb < 4; mb++) {
        const int r0 = warp_m * 64 + mb * 16 + g;
        const float xa = x2[bm + r0], xb = x2[bm + r0 + 8];
        rs[mb][0] = 0.f; rs[mb][1] = 0.f;
#pragma unroll
        for (int nb = 0; nb < 4; nb++) {
            const int cl = warp_n * 32 + nb * 8 + 2 * tig;
            const float2 ca = __half22float2(*reinterpret_cast<const __half2*>(&acc[mb][nb][0]));
            const float2 cb = __half22float2(*reinterpret_cast<const __half2*>(&acc[mb][nb][1]));
            const float p0 = p2s[cl], p1 = p2s[cl + 1];
            const float s0 = scs[cl], s1 = scs[cl + 1];
            const float q0 = fmaxf(xa - 2.f * ca.x + p0, 0.f);
            const float q1 = fmaxf(xa - 2.f * ca.y + p1, 0.f);
            const float q2 = fmaxf(xb - 2.f * cb.x + p0, 0.f);
            const float q3 = fmaxf(xb - 2.f * cb.y + p1, 0.f);
            const float e0 = __expf(s0 / (sqrtf(q0) + 0.1f));
            const float e1 = __expf(s1 / (sqrtf(q1) + 0.1f));
            const float e2 = __expf(s0 / (sqrtf(q2) + 0.1f));
            const float e3 = __expf(s1 / (sqrtf(q3) + 0.1f));
            rs[mb][0] += e0 + e1;
            rs[mb][1] += e2 + e3;
            *reinterpret_cast<__half2*>(Ch + (size_t)(bm + r0) * NNEUR + bn + cl) =
                __floats2half2_rn(e0, e1);
            *reinterpret_cast<__half2*>(Ch + (size_t)(bm + r0 + 8) * NNEUR + bn + cl) =
                __floats2half2_rn(e2, e3);
        }
    }

    // deterministic per-block row sums
#pragma unroll
    for (int mb = 0; mb < 4; mb++) {
#pragma unroll
        for (int h = 0; h < 2; h++) {
            float v = rs[mb][h];
            v += __shfl_down_sync(0xffffffffu, v, 1);
            v += __shfl_down_sync(0xffffffffu, v, 2);
            if (tig == 0)
                bsum[warp_n][warp_m * 64 + mb * 16 + h * 8 + g] = v;
        }
    }
    __syncthreads();
    if (tid < 128) {
        const float s = bsum[0][tid] + bsum[1][tid] + bsum[2][tid] + bsum[3][tid];
        psum[(size_t)(bm + tid) * NBLK1 + blockIdx.x] = s;
    }
}

// ---------------------------------------------------------------------------
// GEMM2: out = (e @ W2) * invS[row] + cvec[col], fp16 in, DUAL fp16 acc sets
// (even/odd k16-step), fp32 combine in epilogue.  niter = NNEUR/32 = 128.
// ---------------------------------------------------------------------------
__global__ __launch_bounds__(256) void gemm2_f16(
    const __half* __restrict__ A, const __half* __restrict__ B,
    float* __restrict__ Cf,
    const float* __restrict__ colv, float* __restrict__ psum)
{
    extern __shared__ __align__(128) char dsm[];
    __shared__ float invs[128], scs[128];

    const int tid  = threadIdx.x;
    const int lane = tid & 31, wid = tid >> 5;
    const int warp_m = wid >> 2, warp_n = wid & 3;
    const int bm = blockIdx.y * 128, bn = blockIdx.x * 128;
    constexpr int NITER = NNEUR / 32;  // 128

    if (tid < 128) scs[tid] = colv[bn + tid];

    const int lrow = tid >> 2;
    const int lchk = tid & 3;
    const uint32_t su = smem_to_u32(dsm);

    auto issue = [&](int slot, int it) {
        const int k0 = it * 32;
        const uint32_t ab = su + slot * 16384;
        const uint32_t bb = ab + 8192;
#pragma unroll
        for (int h = 0; h < 2; h++) {
            const int r = lrow + h * 64;
            cp16(ab + swz_off(r, lchk), A + (size_t)(bm + r) * NNEUR + k0 + lchk * 8);
            cp16(bb + swz_off(r, lchk), B + (size_t)(bn + r) * NNEUR + k0 + lchk * 8);
        }
        CP_COMMIT();
    };

    issue(0, 0);
    issue(1, 1);
    issue(2, 2);

    if (tid < 128) {
        // invS for this CTA's 128 rows (overlaps the prefetches above);
        // same summation order as before -> bit-identical S
        const float4* pp = reinterpret_cast<const float4*>(psum + (size_t)(bm + tid) * NBLK1);
        float s = 0.f;
#pragma unroll
        for (int j = 0; j < NBLK1 / 4; j++) {
            const float4 v = pp[j];
            s += v.x + v.y + v.z + v.w;
        }
        invs[tid] = 1.0f / s;
    }

    uint32_t accE[4][4][2] = {};       // even k16-steps
    uint32_t accO[4][4][2] = {};       // odd  k16-steps
    const int rin = lane & 7, matid = lane >> 3;

    for (int itb = 0; itb < NITER; itb += 4) {
#pragma unroll
        for (int j = 0; j < 4; j++) {
            const int it = itb + j;
            CP_WAIT(2);
            __syncthreads();
            if (it + 3 < NITER) issue((j + 3) & 3, it + 3);

            const uint32_t a_s = su + j * 16384;
            const uint32_t b_s = a_s + 8192;
#pragma unroll
            for (int s = 0; s < 2; s++) {
                uint32_t af[4][4], bf[2][4];
#pragma unroll
                for (int mb = 0; mb < 4; mb++) {
                    const int row = warp_m * 64 + mb * 16 + (matid & 1) * 8 + rin;
                    const int chk = s * 2 + (matid >> 1);
                    ldsm4(af[mb][0], af[mb][1], af[mb][2], af[mb][3], a_s + swz_off(row, chk));
                }
#pragma unroll
                for (int nb2 = 0; nb2 < 2; nb2++) {
                    const int row = warp_n * 32 + nb2 * 16 + (matid >> 1) * 8 + rin;
                    const int chk = s * 2 + (matid & 1);
                    ldsm4(bf[nb2][0], bf[nb2][1], bf[nb2][2], bf[nb2][3], b_s + swz_off(row, chk));
                }
#pragma unroll
                for (int mb = 0; mb < 4; mb++)
#pragma unroll
                    for (int nb = 0; nb < 4; nb++)
                        mma16816h(s == 0 ? accE[mb][nb] : accO[mb][nb], af[mb],
                                  bf[nb >> 1][(nb & 1) * 2], bf[nb >> 1][(nb & 1) * 2 + 1]);
            }
        }
    }

    // ---- epilogue: (E + O) * invS + bias -> fp32 ----
    const int g = lane >> 2, tig = lane & 3;
#pragma unroll
    for (int mb = 0; mb < 4; mb++) {
        const int r0 = warp_m * 64 + mb * 16 + g;
        const float inva = invs[r0], invb = invs[r0 + 8];
#pragma unroll
        for (int nb = 0; nb < 4; nb++) {
            const int cl = warp_n * 32 + nb * 8 + 2 * tig;
            const float2 ea = __half22float2(*reinterpret_cast<const __half2*>(&accE[mb][nb][0]));
            const float2 eb = __half22float2(*reinterpret_cast<const __half2*>(&accE[mb][nb][1]));
            const float2 oa = __half22float2(*reinterpret_cast<const __half2*>(&accO[mb][nb][0]));
            const float2 ob = __half22float2(*reinterpret_cast<const __half2*>(&accO[mb][nb][1]));
            const float b0 = scs[cl], b1 = scs[cl + 1];
            *reinterpret_cast<float2*>(Cf + (size_t)(bm + r0) * DIM + bn + cl) =
                make_float2(fmaf(ea.x + oa.x, inva, b0), fmaf(ea.y + oa.y, inva, b1));
            *reinterpret_cast<float2*>(Cf + (size_t)(bm + r0 + 8) * DIM + bn + cl) =
                make_float2(fmaf(eb.x + ob.x, invb, b0), fmaf(eb.y + ob.y, invb, b1));
        }
    }
}

// ---------------------------------------------------------------------------
// small GEMMs (side stream): fp16 in, fp32 acc, fp16 out.  C = A @ B^T.
// ---------------------------------------------------------------------------
__global__ __launch_bounds__(256) void gemm_small(
    const __half* __restrict__ A, const __half* __restrict__ B,
    __half* __restrict__ Ch, int ldA, int ldB, int ldC, int niter)
{
    extern __shared__ __align__(128) char dsm[];
    const int tid  = threadIdx.x;
    const int lane = tid & 31, wid = tid >> 5;
    const int warp_m = wid >> 2, warp_n = wid & 3;
    const int bm = blockIdx.y * 128, bn = blockIdx.x * 128;

    const int lrow = tid >> 2;
    const int lchk = tid & 3;
    const uint32_t su = smem_to_u32(dsm);

    auto issue = [&](int slot, int it) {
        const int k0 = it * 32;
        const uint32_t ab = su + slot * 16384;
        const uint32_t bb = ab + 8192;
#pragma unroll
        for (int h = 0; h < 2; h++) {
            const int r = lrow + h * 64;
            cp16(ab + swz_off(r, lchk), A + (size_t)(bm + r) * ldA + k0 + lchk * 8);
            cp16(bb + swz_off(r, lchk), B + (size_t)(bn + r) * ldB + k0 + lchk * 8);
        }
        CP_COMMIT();
    };

    issue(0, 0);
    issue(1, 1);
    issue(2, 2);

    float acc[4][4][4] = {};
    const int rin = lane & 7, matid = lane >> 3;

    for (int itb = 0; itb < niter; itb += 4) {
#pragma unroll
        for (int j = 0; j < 4; j++) {
            const int it = itb + j;
            CP_WAIT(2);
            __syncthreads();
            if (it + 3 < niter) issue((j + 3) & 3, it + 3);

            const uint32_t a_s = su + j * 16384;
            const uint32_t b_s = a_s + 8192;
#pragma unroll
            for (int s = 0; s < 2; s++) {
                uint32_t af[4][4], bf[2][4];
#pragma unroll
                for (int mb = 0; mb < 4; mb++) {
                    const int row = warp_m * 64 + mb * 16 + (matid & 1) * 8 + rin;
                    const int chk = s * 2 + (matid >> 1);
                    ldsm4(af[mb][0], af[mb][1], af[mb][2], af[mb][3], a_s + swz_off(row, chk));
                }
#pragma unroll
                for (int nb2 = 0; nb2 < 2; nb2++) {
                    const int row = warp_n * 32 + nb2 * 16 + (matid >> 1) * 8 + rin;
                    const int chk = s * 2 + (matid & 1);
                    ldsm4(bf[nb2][0], bf[nb2][1], bf[nb2][2], bf[nb2][3], b_s + swz_off(row, chk));
                }
#pragma unroll
                for (int mb = 0; mb < 4; mb++)
#pragma unroll
                    for (int nb = 0; nb < 4; nb++)
                        mma16816f(acc[mb][nb], af[mb],
                                  bf[nb >> 1][(nb & 1) * 2], bf[nb >> 1][(nb & 1) * 2 + 1]);
            }
        }
    }

    const int g = lane >> 2, tig = lane & 3;
#pragma unroll
    for (int mb = 0; mb < 4; mb++) {
        const int r0 = warp_m * 64 + mb * 16 + g;
#pragma unroll
        for (int nb = 0; nb < 4; nb++) {
            const int cl = warp_n * 32 + nb * 8 + 2 * tig;
            const float* c = acc[mb][nb];
            *reinterpret_cast<__half2*>(Ch + (size_t)(bm + r0) * ldC + bn + cl) =
                __floats2half2_rn(c[0], c[1]);
            *reinterpret_cast<__half2*>(Ch + (size_t)(bm + r0 + 8) * ldC + bn + cl) =
                __floats2half2_rn(c[2], c[3]);
        }
    }
}

// ---------------------------------------------------------------------------
// conversions
// ---------------------------------------------------------------------------
// merged: x (rows < BT) and pos (rows >= BT): fp32 -> fp16 + row sum-of-squares
__global__ void conv_inputs(const float* __restrict__ x, const float* __restrict__ pos,
                            __half* __restrict__ xh, __half* __restrict__ ph,
                            float* __restrict__ x2, float* __restrict__ p2) {
    const int row = blockIdx.x;
    const int tid = threadIdx.x;
    const bool isx = (row < BT);
    const int r = isx ? row : row - BT;
    const float* src = isx ? x + (size_t)r * DIM : pos + (size_t)r * DIM;
    const float4 v = reinterpret_cast<const float4*>(src)[tid];
    float s = v.x * v.x + v.y * v.y + v.z * v.z + v.w * v.w;

    union { uint2 u; __half2 h[2]; } wh;
    wh.h[0] = __floats2half2_rn(v.x, v.y);
    wh.h[1] = __floats2half2_rn(v.z, v.w);
    reinterpret_cast<uint2*>((isx ? xh : ph) + (size_t)r * DIM)[tid] = wh.u;
#pragma unroll
    for (int off = 16; off > 0; off >>= 1) s += __shfl_down_sync(0xffffffffu, s, off);
    __shared__ float ws[4];
    if ((tid & 31) == 0) ws[tid >> 5] = s;
    __syncthreads();
    if (tid == 0) (isx ? x2 : p2)[r] = ws[0] + ws[1] + ws[2] + ws[3];
}

// merged weight converts: rows < DIM -> w_v, rows >= DIM -> w_o
__global__ void conv_weights(const float* __restrict__ wv, const float* __restrict__ wo,
                             __half* __restrict__ wvh, __half* __restrict__ woh) {
    const int row = blockIdx.x;
    const int tid = threadIdx.x;
    const float* src = (row < DIM) ? wv + (size_t)row * DIM
                                   : wo + (size_t)(row - DIM) * DIM;
    __half* dst = (row < DIM) ? wvh + (size_t)row * DIM
                              : woh + (size_t)(row - DIM) * DIM;
    const float4 v = reinterpret_cast<const float4*>(src)[tid];
    union { uint2 u; __half2 h[2]; } w;
    w.h[0] = __floats2half2_rn(v.x, v.y);
    w.h[1] = __floats2half2_rn(v.z, v.w);
    reinterpret_cast<uint2*>(dst)[tid] = w.u;
}

// cvec[d] = b_o[d] + dot(w_o[d,:], b_v)
__global__ void cvec_kernel(const float* __restrict__ w_o, const float* __restrict__ b_v,
                            const float* __restrict__ b_o, float* __restrict__ cvec) {
    const int d = blockIdx.x;
    const int tid = threadIdx.x;
    float s = 0.f;
#pragma unroll
    for (int i = tid; i < DIM; i += 128) s += w_o[(size_t)d * DIM + i] * b_v[i];
#pragma unroll
    for (int off = 16; off > 0; off >>= 1) s += __shfl_down_sync(0xffffffffu, s, off);
    __shared__ float ws[4];
    if ((tid & 31) == 0) ws[tid >> 5] = s;
    __syncthreads();
    if (tid == 0) cvec[d] = b_o[d] + ws[0] + ws[1] + ws[2] + ws[3];
}

// ---------------------------------------------------------------------------
extern "C" void kernel_launch(void* const* d_in, const int* in_sizes, int n_in,
                              void* d_out, int out_size)
{
    const float* x     = (const float*)d_in[0];
    const float* pos   = (const float*)d_in[1];
    const float* scale = (const float*)d_in[2];
    const float* w_v   = (const float*)d_in[3];
    const float* b_v   = (const float*)d_in[4];
    const float* w_o   = (const float*)d_in[5];
    const float* b_o   = (const float*)d_in[6];
    float* out = (float*)d_out;

    static float* pp2 = nullptr;
    static float *px2, *pcv, *ppsum;
    static __half *pxh, *pph, *pwvh, *pwoh, *pvalh, *pw2h, *pattn;
    static cudaStream_t s1;
    static cudaEvent_t ev0, ev1;
    if (pp2 == nullptr) {
        cudaGetSymbolAddress((void**)&pp2,   g_p2);
        cudaGetSymbolAddress((void**)&px2,   g_x2);
        cudaGetSymbolAddress((void**)&pcv,   g_cvec);
        cudaGetSymbolAddress((void**)&ppsum, g_psum);
        cudaGetSymbolAddress((void**)&pxh,   g_xh);
        cudaGetSymbolAddress((void**)&pph,   g_ph);
        cudaGetSymbolAddress((void**)&pwvh,  g_wvh);
        cudaGetSymbolAddress((void**)&pwoh,  g_woh);
        cudaGetSymbolAddress((void**)&pvalh, g_valh);
        cudaGetSymbolAddress((void**)&pw2h,  g_w2h);
        cudaGetSymbolAddress((void**)&pattn, g_attn);
        cudaFuncSetAttribute(gemm1_f16,  cudaFuncAttributeMaxDynamicSharedMemorySize, MG_SMEM);
        cudaFuncSetAttribute(gemm2_f16,  cudaFuncAttributeMaxDynamicSharedMemorySize, MG_SMEM);
        cudaFuncSetAttribute(gemm_small, cudaFuncAttributeMaxDynamicSharedMemorySize, MG_SMEM);
        cudaStreamCreateWithFlags(&s1, cudaStreamNonBlocking);
        cudaEventCreateWithFlags(&ev0, cudaEventDisableTiming);
        cudaEventCreateWithFlags(&ev1, cudaEventDisableTiming);
    }

    // input converts + norms (needed by both branches)
    conv_inputs<<<BT + NNEUR, 128>>>(x, pos, pxh, pph, px2, pp2);
    cudaEventRecord(ev0, 0);

    // ---- side stream: weight chain (independent of GEMM1) ----
    cudaStreamWaitEvent(s1, ev0, 0);
    conv_weights<<<2 * DIM, 128, 0, s1>>>(w_v, w_o, pwvh, pwoh);
    cvec_kernel <<<DIM,     128, 0, s1>>>(w_o, b_v, b_o, pcv);
    // values = pos @ w_v^T           (4096 x 512, K=512, fp16 out, fp32 acc)
    gemm_small<<<dim3(DIM / 128, NNEUR / 128), 256, MG_SMEM, s1>>>(
        pph, pwvh, pvalh, DIM, DIM, DIM, DIM / 32);
    // W2^T = w_o @ values^T          (512 x 4096, K=512, fp16 out, fp32 acc)
    gemm_small<<<dim3(NNEUR / 128, DIM / 128), 256, MG_SMEM, s1>>>(
        pwoh, pvalh, pw2h, DIM, DIM, NNEUR, DIM / 32);
    cudaEventRecord(ev1, s1);

    // ---- main stream: e = exp(f(x @ pos^T)), fp16 in / fp16 acc ----
    gemm1_f16<<<dim3(NNEUR / 128, BT / 128), 256, MG_SMEM>>>(
        pxh, pph, pattn, px2, pp2, scale, ppsum);

    // join, then out = (e @ W2) / S + cvec  (dual fp16 acc, fp32 combine)
    cudaStreamWaitEvent(0, ev1, 0);
    gemm2_f16<<<dim3(DIM / 128, BT / 128), 256, MG_SMEM>>>(
        pattn, pw2h, out, pcv, ppsum);
}

// round 17
// speedup vs baseline: 1.1435x; 1.1435x over previous
#include <cuda_runtime.h>
#include <cuda_fp16.h>
#include <math.h>
#include <stdint.h>

#define DIM    512
#define NNEUR  4096
#define BT     8192   // B*T
#define NBLK1  (NNEUR / 128)   // 32 column-blocks in GEMM1

// ---------------- scratch (device globals; allocation-free) ----------------
__device__ float                g_p2[NNEUR];
__device__ float                g_x2[BT];
__device__ float                g_cvec[DIM];
__device__ __align__(16) float  g_psum[(size_t)BT * NBLK1];     // 1 MB
__device__ __align__(16) __half g_xh[BT * DIM];                 // 8 MB
__device__ __align__(16) __half g_ph[NNEUR * DIM];              // 4 MB
__device__ __align__(16) __half g_wvh[DIM * DIM];               // 0.5 MB
__device__ __align__(16) __half g_woh[DIM * DIM];               // 0.5 MB
__device__ __align__(16) __half g_valh[NNEUR * DIM];            // 4 MB  values
__device__ __align__(16) __half g_w2h[DIM * NNEUR];             // 4 MB  W2^T
__device__ __align__(16) __half g_attn[(size_t)BT * NNEUR];     // 64 MB (e = exp)

// ---------------- warp-mma helpers (base ISA: sm_80+, no 'a' suffix) -------
__device__ __forceinline__ uint32_t smem_to_u32(const void* p) {
    uint32_t a;
    asm("{ .reg .u64 t; cvta.to.shared.u64 t, %1; cvt.u32.u64 %0, t; }" : "=r"(a) : "l"(p));
    return a;
}
__device__ __forceinline__ void ldsm4(uint32_t& r0, uint32_t& r1, uint32_t& r2,
                                      uint32_t& r3, uint32_t addr) {
    asm volatile("ldmatrix.sync.aligned.m8n8.x4.shared.b16 {%0,%1,%2,%3}, [%4];"
                 : "=r"(r0), "=r"(r1), "=r"(r2), "=r"(r3) : "r"(addr));
}
// f16 inputs, f32 accumulators
__device__ __forceinline__ void mma16816f(float* c, const uint32_t* a,
                                          uint32_t b0, uint32_t b1) {
    asm volatile(
        "mma.sync.aligned.m16n8k16.row.col.f32.f16.f16.f32 "
        "{%0,%1,%2,%3}, {%4,%5,%6,%7}, {%8,%9}, {%0,%1,%2,%3};"
        : "+f"(c[0]), "+f"(c[1]), "+f"(c[2]), "+f"(c[3])
        : "r"(a[0]), "r"(a[1]), "r"(a[2]), "r"(a[3]), "r"(b0), "r"(b1));
}
// f16 inputs, f16 accumulators (2 regs of f16x2)
__device__ __forceinline__ void mma16816h(uint32_t* c, const uint32_t* a,
                                          uint32_t b0, uint32_t b1) {
    asm volatile(
        "mma.sync.aligned.m16n8k16.row.col.f16.f16.f16.f16 "
        "{%0,%1}, {%2,%3,%4,%5}, {%6,%7}, {%0,%1};"
        : "+r"(c[0]), "+r"(c[1])
        : "r"(a[0]), "r"(a[1]), "r"(a[2]), "r"(a[3]), "r"(b0), "r"(b1));
}
__device__ __forceinline__ void cp16(uint32_t dst, const void* src) {
    asm volatile("cp.async.cg.shared.global [%0], [%1], 16;" :: "r"(dst), "l"(src));
}
#define CP_COMMIT() asm volatile("cp.async.commit_group;" ::: "memory")
#define CP_WAIT(n)  asm volatile("cp.async.wait_group %0;" :: "n"(n) : "memory")

// swizzled smem offset for 64B rows (4 x 16B chunks), conflict-free ldmatrix
__device__ __forceinline__ uint32_t swz_off(int row, int chunk) {
    return (uint32_t)(row * 64 + ((chunk ^ ((row >> 1) & 3)) << 4));
}

static constexpr int MG_STAGES = 4;
static constexpr int MG_SMEM   = MG_STAGES * 16384;   // 64 KB dynamic

// ---------------------------------------------------------------------------
// Tiling everywhere: BM=128, BN=128, BK=32, 8 warps (2m x 4n), warp 64x32.
// 4-stage cp.async pipeline with const-folded slots.
// ---------------------------------------------------------------------------

// GEMM1: e = exp(interaction(x @ pos^T)), fp16 in, fp16 acc, e -> fp16,
// per-block row sums -> psum.  niter = DIM/32 = 16.
__global__ __launch_bounds__(256) void gemm1_f16(
    const __half* __restrict__ A, const __half* __restrict__ B,
    __half* __restrict__ Ch,
    const float* __restrict__ x2, const float* __restrict__ p2,
    const float* __restrict__ scale, float* __restrict__ psum)
{
    extern __shared__ __align__(128) char dsm[];
    __shared__ float p2s[128], scs[128];
    __shared__ float bsum[4][128];

    const int tid  = threadIdx.x;
    const int lane = tid & 31, wid = tid >> 5;
    const int warp_m = wid >> 2, warp_n = wid & 3;
    const int bm = blockIdx.y * 128, bn = blockIdx.x * 128;
    constexpr int NITER = DIM / 32;    // 16

    if (tid < 128) {
        p2s[tid] = p2[bn + tid];
        scs[tid] = scale[bn + tid];
    }

    const int lrow = tid >> 2;
    const int lchk = tid & 3;
    const uint32_t su = smem_to_u32(dsm);

    auto issue = [&](int slot, int it) {
        const int k0 = it * 32;
        const uint32_t ab = su + slot * 16384;
        const uint32_t bb = ab + 8192;
#pragma unroll
        for (int h = 0; h < 2; h++) {
            const int r = lrow + h * 64;
            cp16(ab + swz_off(r, lchk), A + (size_t)(bm + r) * DIM + k0 + lchk * 8);
            cp16(bb + swz_off(r, lchk), B + (size_t)(bn + r) * DIM + k0 + lchk * 8);
        }
        CP_COMMIT();
    };

    issue(0, 0);
    issue(1, 1);
    issue(2, 2);

    uint32_t acc[4][4][2] = {};
    const int rin = lane & 7, matid = lane >> 3;

    for (int itb = 0; itb < NITER; itb += 4) {
#pragma unroll
        for (int j = 0; j < 4; j++) {
            const int it = itb + j;
            CP_WAIT(2);
            __syncthreads();
            if (it + 3 < NITER) issue((j + 3) & 3, it + 3);

            const uint32_t a_s = su + j * 16384;
            const uint32_t b_s = a_s + 8192;
#pragma unroll
            for (int s = 0; s < 2; s++) {
                uint32_t af[4][4], bf[2][4];
#pragma unroll
                for (int mb = 0; mb < 4; mb++) {
                    const int row = warp_m * 64 + mb * 16 + (matid & 1) * 8 + rin;
                    const int chk = s * 2 + (matid >> 1);
                    ldsm4(af[mb][0], af[mb][1], af[mb][2], af[mb][3], a_s + swz_off(row, chk));
                }
#pragma unroll
                for (int nb2 = 0; nb2 < 2; nb2++) {
                    const int row = warp_n * 32 + nb2 * 16 + (matid >> 1) * 8 + rin;
                    const int chk = s * 2 + (matid & 1);
                    ldsm4(bf[nb2][0], bf[nb2][1], bf[nb2][2], bf[nb2][3], b_s + swz_off(row, chk));
                }
#pragma unroll
                for (int mb = 0; mb < 4; mb++)
#pragma unroll
                    for (int nb = 0; nb < 4; nb++)
                        mma16816h(acc[mb][nb], af[mb],
                                  bf[nb >> 1][(nb & 1) * 2], bf[nb >> 1][(nb & 1) * 2 + 1]);
            }
        }
    }

    // ---- interaction epilogue (fp32 math from unpacked fp16 accs) ----
    const int g = lane >> 2, tig = lane & 3;
    float rs[4][2];
#pragma unroll
    for (int mb = 0; mb < 4; mb++) {
        const int r0 = warp_m * 64 + mb * 16 + g;
        const float xa = x2[bm + r0], xb = x2[bm + r0 + 8];
        rs[mb][0] = 0.f; rs[mb][1] = 0.f;
#pragma unroll
        for (int nb = 0; nb < 4; nb++) {
            const int cl = warp_n * 32 + nb * 8 + 2 * tig;
            const float2 ca = __half22float2(*reinterpret_cast<const __half2*>(&acc[mb][nb][0]));
            const float2 cb = __half22float2(*reinterpret_cast<const __half2*>(&acc[mb][nb][1]));
            const float p0 = p2s[cl], p1 = p2s[cl + 1];
            const float s0 = scs[cl], s1 = scs[cl + 1];
            const float q0 = fmaxf(xa - 2.f * ca.x + p0, 0.f);
            const float q1 = fmaxf(xa - 2.f * ca.y + p1, 0.f);
            const float q2 = fmaxf(xb - 2.f * cb.x + p0, 0.f);
            const float q3 = fmaxf(xb - 2.f * cb.y + p1, 0.f);
            const float e0 = __expf(s0 / (sqrtf(q0) + 0.1f));
            const float e1 = __expf(s1 / (sqrtf(q1) + 0.1f));
            const float e2 = __expf(s0 / (sqrtf(q2) + 0.1f));
            const float e3 = __expf(s1 / (sqrtf(q3) + 0.1f));
            rs[mb][0] += e0 + e1;
            rs[mb][1] += e2 + e3;
            *reinterpret_cast<__half2*>(Ch + (size_t)(bm + r0) * NNEUR + bn + cl) =
                __floats2half2_rn(e0, e1);
            *reinterpret_cast<__half2*>(Ch + (size_t)(bm + r0 + 8) * NNEUR + bn + cl) =
                __floats2half2_rn(e2, e3);
        }
    }

    // deterministic per-block row sums
#pragma unroll
    for (int mb = 0; mb < 4; mb++) {
#pragma unroll
        for (int h = 0; h < 2; h++) {
            float v = rs[mb][h];
            v += __shfl_down_sync(0xffffffffu, v, 1);
            v += __shfl_down_sync(0xffffffffu, v, 2);
            if (tig == 0)
                bsum[warp_n][warp_m * 64 + mb * 16 + h * 8 + g] = v;
        }
    }
    __syncthreads();
    if (tid < 128) {
        const float s = bsum[0][tid] + bsum[1][tid] + bsum[2][tid] + bsum[3][tid];
        psum[(size_t)(bm + tid) * NBLK1 + blockIdx.x] = s;
    }
}

// ---------------------------------------------------------------------------
// GEMM2: out = (e @ W2) * invS[row] + cvec[col], fp16 in, fp32 acc, fp32 out.
// niter = NNEUR/32 = 128.
// ---------------------------------------------------------------------------
__global__ __launch_bounds__(256) void gemm2_f16(
    const __half* __restrict__ A, const __half* __restrict__ B,
    float* __restrict__ Cf,
    const float* __restrict__ colv, float* __restrict__ psum)
{
    extern __shared__ __align__(128) char dsm[];
    __shared__ float invs[128], scs[128];

    const int tid  = threadIdx.x;
    const int lane = tid & 31, wid = tid >> 5;
    const int warp_m = wid >> 2, warp_n = wid & 3;
    const int bm = blockIdx.y * 128, bn = blockIdx.x * 128;
    constexpr int NITER = NNEUR / 32;  // 128

    if (tid < 128) scs[tid] = colv[bn + tid];

    const int lrow = tid >> 2;
    const int lchk = tid & 3;
    const uint32_t su = smem_to_u32(dsm);

    auto issue = [&](int slot, int it) {
        const int k0 = it * 32;
        const uint32_t ab = su + slot * 16384;
        const uint32_t bb = ab + 8192;
#pragma unroll
        for (int h = 0; h < 2; h++) {
            const int r = lrow + h * 64;
            cp16(ab + swz_off(r, lchk), A + (size_t)(bm + r) * NNEUR + k0 + lchk * 8);
            cp16(bb + swz_off(r, lchk), B + (size_t)(bn + r) * NNEUR + k0 + lchk * 8);
        }
        CP_COMMIT();
    };

    issue(0, 0);
    issue(1, 1);
    issue(2, 2);

    if (tid < 128) {
        // invS for this CTA's 128 rows (overlaps the prefetches above);
        // same summation order as before -> bit-identical S
        const float4* pp = reinterpret_cast<const float4*>(psum + (size_t)(bm + tid) * NBLK1);
        float s = 0.f;
#pragma unroll
        for (int j = 0; j < NBLK1 / 4; j++) {
            const float4 v = pp[j];
            s += v.x + v.y + v.z + v.w;
        }
        invs[tid] = 1.0f / s;
    }

    float acc[4][4][4] = {};
    const int rin = lane & 7, matid = lane >> 3;

    for (int itb = 0; itb < NITER; itb += 4) {
#pragma unroll
        for (int j = 0; j < 4; j++) {
            const int it = itb + j;
            CP_WAIT(2);
            __syncthreads();
            if (it + 3 < NITER) issue((j + 3) & 3, it + 3);

            const uint32_t a_s = su + j * 16384;
            const uint32_t b_s = a_s + 8192;
#pragma unroll
            for (int s = 0; s < 2; s++) {
                uint32_t af[4][4], bf[2][4];
#pragma unroll
                for (int mb = 0; mb < 4; mb++) {
                    const int row = warp_m * 64 + mb * 16 + (matid & 1) * 8 + rin;
                    const int chk = s * 2 + (matid >> 1);
                    ldsm4(af[mb][0], af[mb][1], af[mb][2], af[mb][3], a_s + swz_off(row, chk));
                }
#pragma unroll
                for (int nb2 = 0; nb2 < 2; nb2++) {
                    const int row = warp_n * 32 + nb2 * 16 + (matid >> 1) * 8 + rin;
                    const int chk = s * 2 + (matid & 1);
                    ldsm4(bf[nb2][0], bf[nb2][1], bf[nb2][2], bf[nb2][3], b_s + swz_off(row, chk));
                }
#pragma unroll
                for (int mb = 0; mb < 4; mb++)
#pragma unroll
                    for (int nb = 0; nb < 4; nb++)
                        mma16816f(acc[mb][nb], af[mb],
                                  bf[nb >> 1][(nb & 1) * 2], bf[nb >> 1][(nb & 1) * 2 + 1]);
            }
        }
    }

    // ---- epilogue: c * invS + bias -> fp32 ----
    const int g = lane >> 2, tig = lane & 3;
#pragma unroll
    for (int mb = 0; mb < 4; mb++) {
        const int r0 = warp_m * 64 + mb * 16 + g;
        const float inva = invs[r0], invb = invs[r0 + 8];
#pragma unroll
        for (int nb = 0; nb < 4; nb++) {
            const int cl = warp_n * 32 + nb * 8 + 2 * tig;
            const float* c = acc[mb][nb];
            const float b0 = scs[cl], b1 = scs[cl + 1];
            *reinterpret_cast<float2*>(Cf + (size_t)(bm + r0) * DIM + bn + cl) =
                make_float2(fmaf(c[0], inva, b0), fmaf(c[1], inva, b1));
            *reinterpret_cast<float2*>(Cf + (size_t)(bm + r0 + 8) * DIM + bn + cl) =
                make_float2(fmaf(c[2], invb, b0), fmaf(c[3], invb, b1));
        }
    }
}

// ---------------------------------------------------------------------------
// small GEMMs (side stream): fp16 in, fp32 acc, fp16 out.  C = A @ B^T.
// ---------------------------------------------------------------------------
__global__ __launch_bounds__(256) void gemm_small(
    const __half* __restrict__ A, const __half* __restrict__ B,
    __half* __restrict__ Ch, int ldA, int ldB, int ldC, int niter)
{
    extern __shared__ __align__(128) char dsm[];
    const int tid  = threadIdx.x;
    const int lane = tid & 31, wid = tid >> 5;
    const int warp_m = wid >> 2, warp_n = wid & 3;
    const int bm = blockIdx.y * 128, bn = blockIdx.x * 128;

    const int lrow = tid >> 2;
    const int lchk = tid & 3;
    const uint32_t su = smem_to_u32(dsm);

    auto issue = [&](int slot, int it) {
        const int k0 = it * 32;
        const uint32_t ab = su + slot * 16384;
        const uint32_t bb = ab + 8192;
#pragma unroll
        for (int h = 0; h < 2; h++) {
            const int r = lrow + h * 64;
            cp16(ab + swz_off(r, lchk), A + (size_t)(bm + r) * ldA + k0 + lchk * 8);
            cp16(bb + swz_off(r, lchk), B + (size_t)(bn + r) * ldB + k0 + lchk * 8);
        }
        CP_COMMIT();
    };

    issue(0, 0);
    issue(1, 1);
    issue(2, 2);

    float acc[4][4][4] = {};
    const int rin = lane & 7, matid = lane >> 3;

    for (int itb = 0; itb < niter; itb += 4) {
#pragma unroll
        for (int j = 0; j < 4; j++) {
            const int it = itb + j;
            CP_WAIT(2);
            __syncthreads();
            if (it + 3 < niter) issue((j + 3) & 3, it + 3);

            const uint32_t a_s = su + j * 16384;
            const uint32_t b_s = a_s + 8192;
#pragma unroll
            for (int s = 0; s < 2; s++) {
                uint32_t af[4][4], bf[2][4];
#pragma unroll
                for (int mb = 0; mb < 4; mb++) {
                    const int row = warp_m * 64 + mb * 16 + (matid & 1) * 8 + rin;
                    const int chk = s * 2 + (matid >> 1);
                    ldsm4(af[mb][0], af[mb][1], af[mb][2], af[mb][3], a_s + swz_off(row, chk));
                }
#pragma unroll
                for (int nb2 = 0; nb2 < 2; nb2++) {
                    const int row = warp_n * 32 + nb2 * 16 + (matid >> 1) * 8 + rin;
                    const int chk = s * 2 + (matid & 1);
                    ldsm4(bf[nb2][0], bf[nb2][1], bf[nb2][2], bf[nb2][3], b_s + swz_off(row, chk));
                }
#pragma unroll
                for (int mb = 0; mb < 4; mb++)
#pragma unroll
                    for (int nb = 0; nb < 4; nb++)
                        mma16816f(acc[mb][nb], af[mb],
                                  bf[nb >> 1][(nb & 1) * 2], bf[nb >> 1][(nb & 1) * 2 + 1]);
            }
        }
    }

    const int g = lane >> 2, tig = lane & 3;
#pragma unroll
    for (int mb = 0; mb < 4; mb++) {
        const int r0 = warp_m * 64 + mb * 16 + g;
#pragma unroll
        for (int nb = 0; nb < 4; nb++) {
            const int cl = warp_n * 32 + nb * 8 + 2 * tig;
            const float* c = acc[mb][nb];
            *reinterpret_cast<__half2*>(Ch + (size_t)(bm + r0) * ldC + bn + cl) =
                __floats2half2_rn(c[0], c[1]);
            *reinterpret_cast<__half2*>(Ch + (size_t)(bm + r0 + 8) * ldC + bn + cl) =
                __floats2half2_rn(c[2], c[3]);
        }
    }
}

// ---------------------------------------------------------------------------
// conversions
// ---------------------------------------------------------------------------
// merged: x (rows < BT) and pos (rows >= BT): fp32 -> fp16 + row sum-of-squares
__global__ void conv_inputs(const float* __restrict__ x, const float* __restrict__ pos,
                            __half* __restrict__ xh, __half* __restrict__ ph,
                            float* __restrict__ x2, float* __restrict__ p2) {
    const int row = blockIdx.x;
    const int tid = threadIdx.x;
    const bool isx = (row < BT);
    const int r = isx ? row : row - BT;
    const float* src = isx ? x + (size_t)r * DIM : pos + (size_t)r * DIM;
    const float4 v = reinterpret_cast<const float4*>(src)[tid];
    float s = v.x * v.x + v.y * v.y + v.z * v.z + v.w * v.w;

    union { uint2 u; __half2 h[2]; } wh;
    wh.h[0] = __floats2half2_rn(v.x, v.y);
    wh.h[1] = __floats2half2_rn(v.z, v.w);
    reinterpret_cast<uint2*>((isx ? xh : ph) + (size_t)r * DIM)[tid] = wh.u;
#pragma unroll
    for (int off = 16; off > 0; off >>= 1) s += __shfl_down_sync(0xffffffffu, s, off);
    __shared__ float ws[4];
    if ((tid & 31) == 0) ws[tid >> 5] = s;
    __syncthreads();
    if (tid == 0) (isx ? x2 : p2)[r] = ws[0] + ws[1] + ws[2] + ws[3];
}

// merged weight converts: rows < DIM -> w_v, rows >= DIM -> w_o
__global__ void conv_weights(const float* __restrict__ wv, const float* __restrict__ wo,
                             __half* __restrict__ wvh, __half* __restrict__ woh) {
    const int row = blockIdx.x;
    const int tid = threadIdx.x;
    const float* src = (row < DIM) ? wv + (size_t)row * DIM
                                   : wo + (size_t)(row - DIM) * DIM;
    __half* dst = (row < DIM) ? wvh + (size_t)row * DIM
                              : woh + (size_t)(row - DIM) * DIM;
    const float4 v = reinterpret_cast<const float4*>(src)[tid];
    union { uint2 u; __half2 h[2]; } w;
    w.h[0] = __floats2half2_rn(v.x, v.y);
    w.h[1] = __floats2half2_rn(v.z, v.w);
    reinterpret_cast<uint2*>(dst)[tid] = w.u;
}

// cvec[d] = b_o[d] + dot(w_o[d,:], b_v)
__global__ void cvec_kernel(const float* __restrict__ w_o, const float* __restrict__ b_v,
                            const float* __restrict__ b_o, float* __restrict__ cvec) {
    const int d = blockIdx.x;
    const int tid = threadIdx.x;
    float s = 0.f;
#pragma unroll
    for (int i = tid; i < DIM; i += 128) s += w_o[(size_t)d * DIM + i] * b_v[i];
#pragma unroll
    for (int off = 16; off > 0; off >>= 1) s += __shfl_down_sync(0xffffffffu, s, off);
    __shared__ float ws[4];
    if ((tid & 31) == 0) ws[tid >> 5] = s;
    __syncthreads();
    if (tid == 0) cvec[d] = b_o[d] + ws[0] + ws[1] + ws[2] + ws[3];
}

// ---------------------------------------------------------------------------
extern "C" void kernel_launch(void* const* d_in, const int* in_sizes, int n_in,
                              void* d_out, int out_size)
{
    const float* x     = (const float*)d_in[0];
    const float* pos   = (const float*)d_in[1];
    const float* scale = (const float*)d_in[2];
    const float* w_v   = (const float*)d_in[3];
    const float* b_v   = (const float*)d_in[4];
    const float* w_o   = (const float*)d_in[5];
    const float* b_o   = (const float*)d_in[6];
    float* out = (float*)d_out;

    static float* pp2 = nullptr;
    static float *px2, *pcv, *ppsum;
    static __half *pxh, *pph, *pwvh, *pwoh, *pvalh, *pw2h, *pattn;
    static cudaStream_t s1;
    static cudaEvent_t ev0, ev1;
    if (pp2 == nullptr) {
        cudaGetSymbolAddress((void**)&pp2,   g_p2);
        cudaGetSymbolAddress((void**)&px2,   g_x2);
        cudaGetSymbolAddress((void**)&pcv,   g_cvec);
        cudaGetSymbolAddress((void**)&ppsum, g_psum);
        cudaGetSymbolAddress((void**)&pxh,   g_xh);
        cudaGetSymbolAddress((void**)&pph,   g_ph);
        cudaGetSymbolAddress((void**)&pwvh,  g_wvh);
        cudaGetSymbolAddress((void**)&pwoh,  g_woh);
        cudaGetSymbolAddress((void**)&pvalh, g_valh);
        cudaGetSymbolAddress((void**)&pw2h,  g_w2h);
        cudaGetSymbolAddress((void**)&pattn, g_attn);
        cudaFuncSetAttribute(gemm1_f16,  cudaFuncAttributeMaxDynamicSharedMemorySize, MG_SMEM);
        cudaFuncSetAttribute(gemm2_f16,  cudaFuncAttributeMaxDynamicSharedMemorySize, MG_SMEM);
        cudaFuncSetAttribute(gemm_small, cudaFuncAttributeMaxDynamicSharedMemorySize, MG_SMEM);
        cudaStreamCreateWithFlags(&s1, cudaStreamNonBlocking);
        cudaEventCreateWithFlags(&ev0, cudaEventDisableTiming);
        cudaEventCreateWithFlags(&ev1, cudaEventDisableTiming);
    }

    // ---- side stream: weight converts + cvec depend ONLY on harness inputs ----
    conv_weights<<<2 * DIM, 128, 0, s1>>>(w_v, w_o, pwvh, pwoh);
    cvec_kernel <<<DIM,     128, 0, s1>>>(w_o, b_v, b_o, pcv);

    // ---- main stream: input converts + norms (needed by GEMM1 and values) ----
    conv_inputs<<<BT + NNEUR, 128>>>(x, pos, pxh, pph, px2, pp2);
    cudaEventRecord(ev0, 0);

    // side stream continues: values chain (needs pph from conv_inputs)
    cudaStreamWaitEvent(s1, ev0, 0);
    // values = pos @ w_v^T           (4096 x 512, K=512, fp16 out, fp32 acc)
    gemm_small<<<dim3(DIM / 128, NNEUR / 128), 256, MG_SMEM, s1>>>(
        pph, pwvh, pvalh, DIM, DIM, DIM, DIM / 32);
    // W2^T = w_o @ values^T          (512 x 4096, K=512, fp16 out, fp32 acc)
    gemm_small<<<dim3(NNEUR / 128, DIM / 128), 256, MG_SMEM, s1>>>(
        pwoh, pvalh, pw2h, DIM, DIM, NNEUR, DIM / 32);
    cudaEventRecord(ev1, s1);

    // ---- main stream: e = exp(f(x @ pos^T)), fp16 in / fp16 acc ----
    gemm1_f16<<<dim3(NNEUR / 128, BT / 128), 256, MG_SMEM>>>(
        pxh, pph, pattn, px2, pp2, scale, ppsum);

    // join, then out = (e @ W2) / S + cvec  (fp16 in, fp32 acc)
    cudaStreamWaitEvent(0, ev1, 0);
    gemm2_f16<<<dim3(DIM / 128, BT / 128), 256, MG_SMEM>>>(
        pattn, pw2h, out, pcv, ppsum);
}